// round 6
// baseline (speedup 1.0000x reference)
#include <cuda_runtime.h>
#include <math.h>

#define Bsz 256
#define Tt  500
#define Ii  128
#define Hh  512
#define CLIPV 5.0f

#define NBLK 128        // 32 m-tiles x 4 batch-tiles, 1 block/SM
#define NTHR 512        // 8 K-splits x 64 threads
#define MT   16         // m columns per block (x3 gates)
#define BT   64         // batches per block
#define KTOT 640        // 512 (h) + 128 (x)
#define NSPL 8
#define KPS  80         // kk per split
#define CH   16         // kk per chunk
#define NCHK 5          // chunks per split

// smem:
//  W01: ulonglong2[640][8]   81920 B
//  W2 : ull       [640][8]   40960 B
//  Hst: float [8 spl][2 buf][16 kk][64 b]  65536 B  (reused as reduction arena)
#define SM_W01 0
#define SM_W2  81920
#define SM_HS  (81920 + 40960)
#define HS_SPL (2 * CH * 64 * 4)          // 8192 per split
#define SMEM_BYTES (SM_HS + NSPL * HS_SPL)  // 188416

typedef unsigned long long ull;

__device__ float    g_h[2][Bsz * Hh];
__device__ unsigned g_cnt   = 0;
__device__ unsigned g_phase = 0;

__device__ __forceinline__ ull fma2(ull a, ull b, ull c) {
    ull d;
    asm("fma.rn.f32x2 %0, %1, %2, %3;" : "=l"(d) : "l"(a), "l"(b), "l"(c));
    return d;
}
__device__ __forceinline__ ull add2(ull a, ull b) {
    ull d;
    asm("add.rn.f32x2 %0, %1, %2;" : "=l"(d) : "l"(a), "l"(b));
    return d;
}
__device__ __forceinline__ ull pack2(float a, float b) {
    ull d;
    asm("mov.b64 %0, {%1, %2};" : "=l"(d) : "f"(a), "f"(b));
    return d;
}
__device__ __forceinline__ ull dup2(float f) {
    ull d;
    asm("mov.b64 %0, {%1, %1};" : "=l"(d) : "f"(f));
    return d;
}
__device__ __forceinline__ float lo2(ull v) { return __uint_as_float((unsigned)v); }
__device__ __forceinline__ float hi2(ull v) { return __uint_as_float((unsigned)(v >> 32)); }
__device__ __forceinline__ float sigf(float x) { return 1.f / (1.f + __expf(-x)); }

__global__ void __launch_bounds__(NTHR, 1) gru_persist(
    const float* __restrict__ x,      // (B, T, I)
    const float* __restrict__ h0,     // (B, H)
    const float* __restrict__ w_ih,   // (3H, I)
    const float* __restrict__ w_hh,   // (3H, H)
    const float* __restrict__ b_ih,   // (3H)
    const float* __restrict__ b_hh,   // (3H)
    float* __restrict__ out)          // (B, T, H) then (B, H) tail
{
    extern __shared__ char sm[];
    ulonglong2* W01 = (ulonglong2*)(sm + SM_W01);   // [k*8 + tx]
    ull*        W2  = (ull*)(sm + SM_W2);           // [k*8 + tx]
    ull*        red = (ull*)(sm + SM_HS);           // reduction arena (reuses staging)

    const int tid   = threadIdx.x;
    const int split = tid >> 6;          // 0..7 (K-split)
    const int ltid  = tid & 63;
    const int barid = split + 1;

    float* Hst = (float*)(sm + SM_HS + split * HS_SPL);   // [buf][kk][64]

    const int bm  = blockIdx.x & 31;    // 32 m-tiles
    const int bb  = blockIdx.x >> 5;    // 4 batch-tiles
    const int m0  = bm * MT;
    const int b0  = bb * BT;
    const int tx  = ltid & 7;           // m-pair lane: m = m0 + 2*tx
    const int TY  = ltid >> 3;          // batch octet: b = b0 + 8*TY + 0..7
    const int m   = m0 + 2 * tx;

    unsigned bar_base = 0;
    if (tid == 0)
        asm volatile("ld.global.cg.u32 %0, [%1];" : "=r"(bar_base) : "l"(&g_phase));

    // ---- one-time: weight slice -> smem, transposed to [k][m-pair] ----
    for (int s = tid; s < KTOT * 8; s += NTHR) {
        const int kk = s >> 3, txx = s & 7, mm = m0 + 2 * txx;
        float wr0, wr1, wz0, wz1, wn0, wn1;
        if (kk < Hh) {
            wr0 = w_hh[(0 * Hh + mm) * Hh + kk]; wr1 = w_hh[(0 * Hh + mm + 1) * Hh + kk];
            wz0 = w_hh[(1 * Hh + mm) * Hh + kk]; wz1 = w_hh[(1 * Hh + mm + 1) * Hh + kk];
            wn0 = w_hh[(2 * Hh + mm) * Hh + kk]; wn1 = w_hh[(2 * Hh + mm + 1) * Hh + kk];
        } else {
            const int kx = kk - Hh;
            wr0 = w_ih[(0 * Hh + mm) * Ii + kx]; wr1 = w_ih[(0 * Hh + mm + 1) * Ii + kx];
            wz0 = w_ih[(1 * Hh + mm) * Ii + kx]; wz1 = w_ih[(1 * Hh + mm + 1) * Ii + kx];
            wn0 = w_ih[(2 * Hh + mm) * Ii + kx]; wn1 = w_ih[(2 * Hh + mm + 1) * Ii + kx];
        }
        W01[kk * 8 + txx] = make_ulonglong2(pack2(wr0, wr1), pack2(wz0, wz1));
        W2[kk * 8 + txx]  = pack2(wn0, wn1);
    }

    const float2 cR  = make_float2(b_ih[m] + b_hh[m],           b_ih[m + 1] + b_hh[m + 1]);
    const float2 cZ  = make_float2(b_ih[Hh + m] + b_hh[Hh + m], b_ih[Hh + m + 1] + b_hh[Hh + m + 1]);
    const float2 cNx = make_float2(b_ih[2 * Hh + m],            b_ih[2 * Hh + m + 1]);
    const float2 cNh = make_float2(b_hh[2 * Hh + m],            b_hh[2 * Hh + m + 1]);

    __syncthreads();

    const int k0s = split * KPS;        // split's first global k

    float4 st_regs[4];                  // staging: 16 k-floats of batch-row ltid

    for (int t = 0; t < Tt; t++) {
        const float* hsrc = (t == 0) ? h0 : g_h[t & 1];
        float*       hdst = g_h[(t + 1) & 1];

        ull aR[8], aZ[8], aNh[8], aNx[8];
        #pragma unroll
        for (int j = 0; j < 8; j++) { aR[j] = 0; aZ[j] = 0; aNh[j] = 0; aNx[j] = 0; }

        auto ldg_chunk = [&](int c) {   // chunk c of this split; row = batch ltid
            const int gk = k0s + c * CH;
            const float* p = (gk < Hh)
                ? hsrc + (size_t)(b0 + ltid) * Hh + gk
                : x + ((size_t)(b0 + ltid) * Tt + t) * Ii + (gk - Hh);
            #pragma unroll
            for (int j = 0; j < 4; j++)
                st_regs[j] = __ldcg((const float4*)(p + j * 4));
        };
        auto sts_chunk = [&](int buf) {
            float* H = Hst + buf * (CH * 64);
            #pragma unroll
            for (int j = 0; j < 4; j++) {
                H[(4 * j + 0) * 64 + ltid] = st_regs[j].x;
                H[(4 * j + 1) * 64 + ltid] = st_regs[j].y;
                H[(4 * j + 2) * 64 + ltid] = st_regs[j].z;
                H[(4 * j + 3) * 64 + ltid] = st_regs[j].w;
            }
        };
        auto compute = [&](int buf, int c) {
            const float* H = Hst + buf * (CH * 64);
            const int kc = k0s + c * CH;
            const bool hphase = (kc < Hh);
            #pragma unroll 8
            for (int kk = 0; kk < CH; kk++) {
                ulonglong2 w01 = W01[(kc + kk) * 8 + tx];
                ull        w2v = W2[(kc + kk) * 8 + tx];
                float4 hA = *(const float4*)(H + kk * 64 + 8 * TY);
                float4 hB = *(const float4*)(H + kk * 64 + 8 * TY + 4);
                float hv[8] = {hA.x, hA.y, hA.z, hA.w, hB.x, hB.y, hB.z, hB.w};
                #pragma unroll
                for (int j = 0; j < 8; j++) {
                    ull d = dup2(hv[j]);
                    aR[j] = fma2(d, w01.x, aR[j]);
                    aZ[j] = fma2(d, w01.y, aZ[j]);
                    if (hphase) aNh[j] = fma2(d, w2v, aNh[j]);
                    else        aNx[j] = fma2(d, w2v, aNx[j]);
                }
            }
        };

        // per-split double-buffered chunk pipeline
        ldg_chunk(0);
        sts_chunk(0);
        ldg_chunk(1);
        asm volatile("bar.sync %0, 64;" :: "r"(barid) : "memory");
        #pragma unroll
        for (int i = 0; i < NCHK; i++) {
            const int buf = i & 1;
            if (i + 1 < NCHK) sts_chunk((i + 1) & 1);
            if (i + 2 < NCHK) ldg_chunk(i + 2);
            compute(buf, i);
            asm volatile("bar.sync %0, 64;" :: "r"(barid) : "memory");
        }

        // ---- tree reduction over 8 splits (reuses staging arena) ----
        // region g: red[g*2048 + i*64 + ltid], i = 0..31
        __syncthreads();
        if (split >= 4) {
            const int g = split - 4;
            #pragma unroll
            for (int j = 0; j < 8; j++) {
                red[g * 2048 + (j)      * 64 + ltid] = aR[j];
                red[g * 2048 + (8 + j)  * 64 + ltid] = aZ[j];
                red[g * 2048 + (16 + j) * 64 + ltid] = aNh[j];
                red[g * 2048 + (24 + j) * 64 + ltid] = aNx[j];
            }
        }
        __syncthreads();
        if (split < 4) {
            const int g = split;
            #pragma unroll
            for (int j = 0; j < 8; j++) {
                aR[j]  = add2(aR[j],  red[g * 2048 + (j)      * 64 + ltid]);
                aZ[j]  = add2(aZ[j],  red[g * 2048 + (8 + j)  * 64 + ltid]);
                aNh[j] = add2(aNh[j], red[g * 2048 + (16 + j) * 64 + ltid]);
                aNx[j] = add2(aNx[j], red[g * 2048 + (24 + j) * 64 + ltid]);
            }
        }
        __syncthreads();
        if (split == 2 || split == 3) {
            const int g = split - 2;
            #pragma unroll
            for (int j = 0; j < 8; j++) {
                red[g * 2048 + (j)      * 64 + ltid] = aR[j];
                red[g * 2048 + (8 + j)  * 64 + ltid] = aZ[j];
                red[g * 2048 + (16 + j) * 64 + ltid] = aNh[j];
                red[g * 2048 + (24 + j) * 64 + ltid] = aNx[j];
            }
        }
        __syncthreads();
        if (split < 2) {
            const int g = split;
            #pragma unroll
            for (int j = 0; j < 8; j++) {
                aR[j]  = add2(aR[j],  red[g * 2048 + (j)      * 64 + ltid]);
                aZ[j]  = add2(aZ[j],  red[g * 2048 + (8 + j)  * 64 + ltid]);
                aNh[j] = add2(aNh[j], red[g * 2048 + (16 + j) * 64 + ltid]);
                aNx[j] = add2(aNx[j], red[g * 2048 + (24 + j) * 64 + ltid]);
            }
        }
        __syncthreads();
        if (split == 1) {
            #pragma unroll
            for (int j = 0; j < 8; j++) {
                red[(j)      * 64 + ltid] = aR[j];
                red[(8 + j)  * 64 + ltid] = aZ[j];
                red[(16 + j) * 64 + ltid] = aNh[j];
                red[(24 + j) * 64 + ltid] = aNx[j];
            }
        }
        __syncthreads();

        if (split == 0) {
            #pragma unroll
            for (int j = 0; j < 8; j++) {
                aR[j]  = add2(aR[j],  red[(j)      * 64 + ltid]);
                aZ[j]  = add2(aZ[j],  red[(8 + j)  * 64 + ltid]);
                aNh[j] = add2(aNh[j], red[(16 + j) * 64 + ltid]);
                aNx[j] = add2(aNx[j], red[(24 + j) * 64 + ltid]);
            }
            // ---- gates epilogue: 8 batches x 1 m-pair per thread ----
            #pragma unroll
            for (int j = 0; j < 8; j++) {
                const int b = b0 + 8 * TY + j;
                float2 hp = __ldcg((const float2*)(hsrc + (size_t)b * Hh + m));

                float rl = sigf(lo2(aR[j]) + cR.x);
                float rh = sigf(hi2(aR[j]) + cR.y);
                float zl = sigf(lo2(aZ[j]) + cZ.x);
                float zh = sigf(hi2(aZ[j]) + cZ.y);
                float nl = tanhf(lo2(aNx[j]) + cNx.x + rl * (lo2(aNh[j]) + cNh.x));
                float nh = tanhf(hi2(aNx[j]) + cNx.y + rh * (hi2(aNh[j]) + cNh.y));

                float hl  = (1.f - zl) * nl + zl * hp.x;
                float hhv = (1.f - zh) * nh + zh * hp.y;
                hl  = fminf(fmaxf(hl,  -CLIPV), CLIPV);
                hhv = fminf(fmaxf(hhv, -CLIPV), CLIPV);

                float2 res = make_float2(hl, hhv);
                __stcg((float2*)(hdst + (size_t)b * Hh + m), res);
                *(float2*)(out + ((size_t)b * Tt + t) * Hh + m) = res;
                if (t == Tt - 1)
                    *(float2*)(out + (size_t)Bsz * Tt * Hh + (size_t)b * Hh + m) = res;
            }
        }

        // ---- grid barrier (monotonic phase, wrap-safe) ----
        __syncthreads();
        if (tid == 0) {
            __threadfence();
            unsigned old = atomicAdd(&g_cnt, 1u);
            if (old == (unsigned)(NBLK - 1)) {
                atomicExch(&g_cnt, 0u);
                __threadfence();
                atomicAdd(&g_phase, 1u);
            } else {
                const unsigned tgt = bar_base + (unsigned)(t + 1);
                unsigned v;
                do {
                    __nanosleep(32);
                    asm volatile("ld.global.cg.u32 %0, [%1];" : "=r"(v) : "l"(&g_phase));
                } while ((int)(v - tgt) < 0);
            }
            __threadfence();
        }
        __syncthreads();
    }
}

extern "C" void kernel_launch(void* const* d_in, const int* in_sizes, int n_in,
                              void* d_out, int out_size)
{
    (void)in_sizes; (void)n_in; (void)out_size;
    const float* x    = (const float*)d_in[0];
    const float* h0   = (const float*)d_in[1];
    const float* w_ih = (const float*)d_in[2];
    const float* w_hh = (const float*)d_in[3];
    const float* b_ih = (const float*)d_in[4];
    const float* b_hh = (const float*)d_in[5];
    float* out = (float*)d_out;

    cudaFuncSetAttribute(gru_persist, cudaFuncAttributeMaxDynamicSharedMemorySize,
                         SMEM_BYTES);

    gru_persist<<<NBLK, NTHR, SMEM_BYTES>>>(x, h0, w_ih, w_hh, b_ih, b_hh, out);
}